// round 14
// baseline (speedup 1.0000x reference)
#include <cuda_runtime.h>
#include <cuda_bf16.h>
#include <cstdint>

// Problem constants
#define MAXN 50000
#define MAXE 500000
#define HDIM 128

// ---------------- scratch (device globals) -----------------------------------
__device__ int   g_is64;
__device__ int   g_counts [MAXN];
__device__ int   g_offsets[MAXN + 1];
__device__ int   g_cursor [MAXN];
__device__ int   g_sorted [MAXE];
__device__ int   g_bsum   [256];
__device__ int   g_boff   [256];
__device__ int   g_total;
// bf16 split weights, [c][o][k256]: k<128 -> Wroot[o][k], else Wrel[o][k-128]
__device__ __nv_bfloat16 g_whi[4 * 128 * 256];
__device__ __nv_bfloat16 g_wlo[4 * 128 * 256];

// ---------------- helpers ------------------------------------------------------
__device__ __forceinline__ uint32_t smem_u32(const void* p) {
    uint32_t a;
    asm("{ .reg .u64 t; cvta.to.shared.u64 t, %1; cvt.u32.u64 %0, t; }"
        : "=r"(a) : "l"(p));
    return a;
}

__device__ __forceinline__ void ldsm_x4(uint32_t* r, uint32_t addr) {
    asm volatile("ldmatrix.sync.aligned.m8n8.x4.shared.b16 {%0,%1,%2,%3}, [%4];"
                 : "=r"(r[0]), "=r"(r[1]), "=r"(r[2]), "=r"(r[3]) : "r"(addr));
}
__device__ __forceinline__ void mma_bf16(float* d, const uint32_t* a,
                                         uint32_t b0, uint32_t b1) {
    asm volatile(
        "mma.sync.aligned.m16n8k16.row.col.f32.bf16.bf16.f32 "
        "{%0,%1,%2,%3}, {%4,%5,%6,%7}, {%8,%9}, {%0,%1,%2,%3};"
        : "+f"(d[0]), "+f"(d[1]), "+f"(d[2]), "+f"(d[3])
        : "r"(a[0]), "r"(a[1]), "r"(a[2]), "r"(a[3]), "r"(b0), "r"(b1));
}

// ---------------- CSR kernels --------------------------------------------------
__global__ void detect_kernel(const void* __restrict__ ei, int e, int n) {
    const long long* p64 = (const long long*)ei;
    int cnt = e < 256 ? e : 256;
    int ok = 1;
    for (int i = 0; i < cnt; i++) {
        long long v = p64[i];
        if (v < 0 || v >= (long long)n) { ok = 0; break; }
    }
    g_is64 = ok;
}

__global__ void zero_counts_kernel(int n) {
    int i = blockIdx.x * blockDim.x + threadIdx.x;
    if (i < n) g_counts[i] = 0;
}

__global__ void count_kernel(const void* __restrict__ ei, int e) {
    int i = blockIdx.x * blockDim.x + threadIdx.x;
    if (i < e) {
        int r;
        if (g_is64) r = (int)((const long long*)ei)[i];
        else        r = ((const int*)ei)[i];
        atomicAdd(&g_counts[r], 1);
    }
}

__global__ void scan1_kernel(int n) {
    int tid  = threadIdx.x;
    int gid  = blockIdx.x * 256 + tid;
    int lane = tid & 31;
    int wid  = tid >> 5;
    int v = (gid < n) ? g_counts[gid] : 0;
    int s = v;
#pragma unroll
    for (int o = 1; o < 32; o <<= 1) {
        int t = __shfl_up_sync(0xFFFFFFFFu, s, o);
        if (lane >= o) s += t;
    }
    __shared__ int wtot[8];
    __shared__ int woff[8];
    if (lane == 31) wtot[wid] = s;
    __syncthreads();
    if (tid == 0) {
        int r = 0;
#pragma unroll
        for (int w = 0; w < 8; w++) { woff[w] = r; r += wtot[w]; }
        g_bsum[blockIdx.x] = r;
    }
    __syncthreads();
    int excl = s - v + woff[wid];
    if (gid < n) g_offsets[gid] = excl;
}

__global__ void scan2_kernel(int nb) {
    int tid  = threadIdx.x;
    int lane = tid & 31;
    int wid  = tid >> 5;
    int v = (tid < nb) ? g_bsum[tid] : 0;
    int s = v;
#pragma unroll
    for (int o = 1; o < 32; o <<= 1) {
        int t = __shfl_up_sync(0xFFFFFFFFu, s, o);
        if (lane >= o) s += t;
    }
    __shared__ int wtot[8];
    __shared__ int woff[8];
    if (lane == 31) wtot[wid] = s;
    __syncthreads();
    if (tid == 0) {
        int r = 0;
#pragma unroll
        for (int w = 0; w < 8; w++) { woff[w] = r; r += wtot[w]; }
        g_total = r;
    }
    __syncthreads();
    g_boff[tid] = s - v + woff[wid];
}

__global__ void scan3_kernel(int n) {
    int gid = blockIdx.x * 256 + threadIdx.x;
    if (gid < n) {
        int off = g_offsets[gid] + g_boff[gid >> 8];
        g_offsets[gid] = off;
        g_cursor[gid]  = off;
    }
    if (gid == 0) g_offsets[n] = g_total;
}

__global__ void fill_kernel(const void* __restrict__ ei, int e) {
    int i = blockIdx.x * blockDim.x + threadIdx.x;
    if (i < e) {
        int r, c;
        if (g_is64) {
            const long long* p = (const long long*)ei;
            r = (int)p[i];
            c = (int)p[(size_t)e + i];
        } else {
            const int* p = (const int*)ei;
            r = p[i];
            c = p[(size_t)e + i];
        }
        int pos = atomicAdd(&g_cursor[r], 1);
        g_sorted[pos] = c;
    }
}

// weight prep: bf16 hi/lo split, [c][o][k256]
__global__ void wprep_kernel(const float* __restrict__ Wsrel,
                             const float* __restrict__ Wsroot,
                             const float* __restrict__ Wvrel,
                             const float* __restrict__ Wvroot) {
    int idx = blockIdx.x * blockDim.x + threadIdx.x;
    const int total = 4 * 128 * 256;
    if (idx >= total) return;
    int k = idx & 255;
    int o = (idx >> 8) & 127;
    int c = idx >> 15;
    const float* root = (c == 0) ? Wsroot : Wvroot;
    const float* rel  = (c == 0) ? Wsrel  : Wvrel;
    float w = (k < 128) ? root[o * 128 + k] : rel[o * 128 + (k - 128)];
    __nv_bfloat16 hi = __float2bfloat16(w);
    __nv_bfloat16 lo = __float2bfloat16(w - __bfloat162float(hi));
    g_whi[idx] = hi;
    g_wlo[idx] = lo;
}

// ---------------- fused agg + HMMA GEMM ----------------------------------------
// grid (ceil(n/128), 4), 256 threads (8 warps 4x2), dyn smem 64KB.
// out[n,c,:] = x(n,c,:) @ Wroot_c^T + (sum_{j in N(n)} x(j,c,:)) @ Wrel_c^T
//              (+bias if c==0), bf16 split 3-product via mma.sync.
// A chunks 0,1 load x rows directly; chunks 2,3 GATHER+SUM neighbor rows
// in-kernel (warp-per-node, lane = float2 k-slot) and write the bf16 hi/lo
// split straight into the swizzled tile — no g_agg round trip.

#define SM_AHI 0
#define SM_ALO 16384
#define SM_BHI 32768
#define SM_BLO 49152
#define SM_TOT 65536

__global__ __launch_bounds__(256) void hmma_gemm_kernel(const float* __restrict__ x,
                                                        const float* __restrict__ bias,
                                                        float* __restrict__ out,
                                                        int n) {
    extern __shared__ char smem[];
    uint32_t sb = smem_u32(smem);

    int tid  = threadIdx.x;
    int lane = tid & 31;
    int warp = tid >> 5;
    int wm   = warp & 3;     // 0..3  -> 32 M rows each
    int wn   = warp >> 2;    // 0..1  -> 64 N cols each
    int c    = blockIdx.y;
    int row0 = blockIdx.x * 128;

    int q   = lane >> 3;     // ldmatrix lane group
    int rib = lane & 7;
    int qm  = (q & 1) * 8;
    int qk  = q >> 1;

    // fixed ldmatrix row indices
    int rA0 = wm * 32 + qm + rib;
    int rA1 = rA0 + 16;
    int rB[4];
#pragma unroll
    for (int p = 0; p < 4; p++) rB[p] = wn * 64 + p * 16 + qm + rib;

    float acc[2][8][4];
#pragma unroll
    for (int mt = 0; mt < 2; mt++)
#pragma unroll
        for (int nt = 0; nt < 8; nt++)
#pragma unroll
            for (int i = 0; i < 4; i++) acc[mt][nt][i] = 0.f;

    for (int k0c = 0; k0c < 4; k0c++) {
        if (k0c) __syncthreads();   // protect smem reuse

        int kbase = (k0c & 1) * 64;

        if (k0c < 2) {
            // ---- A chunk from x: 128 rows x 64 k fp32 -> bf16 hi/lo swizzled ----
#pragma unroll
            for (int it = 0; it < 8; it++) {
                int idx = it * 256 + tid;
                int r   = idx >> 4;           // 0..127
                int f4  = idx & 15;           // float4 within row
                float4 v = make_float4(0.f, 0.f, 0.f, 0.f);
                int nn = row0 + r;
                if (nn < n)
                    v = *(const float4*)&x[((size_t)nn * 4 + c) * 128 + kbase + f4 * 4];
                __nv_bfloat16 h0 = __float2bfloat16(v.x);
                __nv_bfloat16 h1 = __float2bfloat16(v.y);
                __nv_bfloat16 h2 = __float2bfloat16(v.z);
                __nv_bfloat16 h3 = __float2bfloat16(v.w);
                __nv_bfloat16 l0 = __float2bfloat16(v.x - __bfloat162float(h0));
                __nv_bfloat16 l1 = __float2bfloat16(v.y - __bfloat162float(h1));
                __nv_bfloat16 l2 = __float2bfloat16(v.z - __bfloat162float(h2));
                __nv_bfloat16 l3 = __float2bfloat16(v.w - __bfloat162float(h3));
                uint2 hv, lv;
                hv.x = (uint32_t)__bfloat16_as_ushort(h0) | ((uint32_t)__bfloat16_as_ushort(h1) << 16);
                hv.y = (uint32_t)__bfloat16_as_ushort(h2) | ((uint32_t)__bfloat16_as_ushort(h3) << 16);
                lv.x = (uint32_t)__bfloat16_as_ushort(l0) | ((uint32_t)__bfloat16_as_ushort(l1) << 16);
                lv.y = (uint32_t)__bfloat16_as_ushort(l2) | ((uint32_t)__bfloat16_as_ushort(l3) << 16);
                int kc   = f4 >> 1;
                int sub8 = (f4 & 1) << 3;
                uint32_t off = (uint32_t)(r * 128 + ((kc ^ (r & 7)) << 4) + sub8);
                *(uint2*)(smem + SM_AHI + off) = hv;
                *(uint2*)(smem + SM_ALO + off) = lv;
            }
        } else {
            // ---- A chunk from neighbor aggregation (fused gather) ----
            // warp w owns nodes [w*16, w*16+16); lane owns float2 k-slot 2l..2l+1
            const float2* xv2 = (const float2*)x;
            int koff2 = c * 64 + (kbase >> 1) + lane;   // float2 index in node row
#pragma unroll 4
            for (int i = 0; i < 16; i++) {
                int r  = warp * 16 + i;
                int nn = row0 + r;
                float2 a2 = make_float2(0.f, 0.f);
                if (nn < n) {
                    int beg = g_offsets[nn];
                    int end = g_offsets[nn + 1];
                    int j = beg;
                    for (; j + 3 < end; j += 4) {
                        int c0 = g_sorted[j];
                        int c1 = g_sorted[j + 1];
                        int c2 = g_sorted[j + 2];
                        int c3 = g_sorted[j + 3];
                        float2 v0 = xv2[(size_t)c0 * 256 + koff2];
                        float2 v1 = xv2[(size_t)c1 * 256 + koff2];
                        float2 v2 = xv2[(size_t)c2 * 256 + koff2];
                        float2 v3 = xv2[(size_t)c3 * 256 + koff2];
                        a2.x += v0.x + v1.x + v2.x + v3.x;
                        a2.y += v0.y + v1.y + v2.y + v3.y;
                    }
                    for (; j < end; j++) {
                        int c0 = g_sorted[j];
                        float2 v0 = xv2[(size_t)c0 * 256 + koff2];
                        a2.x += v0.x;
                        a2.y += v0.y;
                    }
                }
                __nv_bfloat16 h0 = __float2bfloat16(a2.x);
                __nv_bfloat16 h1 = __float2bfloat16(a2.y);
                __nv_bfloat16 l0 = __float2bfloat16(a2.x - __bfloat162float(h0));
                __nv_bfloat16 l1 = __float2bfloat16(a2.y - __bfloat162float(h1));
                uint32_t hv = (uint32_t)__bfloat16_as_ushort(h0) | ((uint32_t)__bfloat16_as_ushort(h1) << 16);
                uint32_t lv = (uint32_t)__bfloat16_as_ushort(l0) | ((uint32_t)__bfloat16_as_ushort(l1) << 16);
                int kc  = lane >> 2;               // 16B chunk
                int sub = (lane & 3) << 2;         // byte within chunk
                uint32_t off = (uint32_t)(r * 128 + ((kc ^ (r & 7)) << 4) + sub);
                *(uint32_t*)(smem + SM_AHI + off) = hv;
                *(uint32_t*)(smem + SM_ALO + off) = lv;
            }
        }

        // ---- B chunk: 128 n x 64 k bf16 hi/lo swizzled ----
        const __nv_bfloat16* wh = g_whi + (size_t)c * 128 * 256 + k0c * 64;
        const __nv_bfloat16* wl = g_wlo + (size_t)c * 128 * 256 + k0c * 64;
#pragma unroll
        for (int it = 0; it < 4; it++) {
            int id = it * 256 + tid;
            int nr = id >> 3;             // 0..127
            int kc = id & 7;              // 16B chunk
            uint4 hv = *(const uint4*)&wh[(size_t)nr * 256 + kc * 8];
            uint4 lv = *(const uint4*)&wl[(size_t)nr * 256 + kc * 8];
            uint32_t off = (uint32_t)(nr * 128 + ((kc ^ (nr & 7)) << 4));
            *(uint4*)(smem + SM_BHI + off) = hv;
            *(uint4*)(smem + SM_BLO + off) = lv;
        }

        __syncthreads();

        // ---- compute: per k-step load all fragments once, 3 products ----
#pragma unroll
        for (int ks = 0; ks < 4; ks++) {
            int kc = ks * 2 + qk;
            uint32_t ah0[4], ah1[4], al0[4], al1[4];
            uint32_t offA0 = (uint32_t)(rA0 * 128 + ((kc ^ (rA0 & 7)) << 4));
            uint32_t offA1 = (uint32_t)(rA1 * 128 + ((kc ^ (rA1 & 7)) << 4));
            ldsm_x4(ah0, sb + SM_AHI + offA0);
            ldsm_x4(ah1, sb + SM_AHI + offA1);
            ldsm_x4(al0, sb + SM_ALO + offA0);
            ldsm_x4(al1, sb + SM_ALO + offA1);
            uint32_t bh[4][4], bl[4][4];
#pragma unroll
            for (int pr = 0; pr < 4; pr++) {
                uint32_t offB = (uint32_t)(rB[pr] * 128 + ((kc ^ (rB[pr] & 7)) << 4));
                ldsm_x4(bh[pr], sb + SM_BHI + offB);
                ldsm_x4(bl[pr], sb + SM_BLO + offB);
            }
#pragma unroll
            for (int pr = 0; pr < 4; pr++) {
                // hi * hi
                mma_bf16(acc[0][pr * 2],     ah0, bh[pr][0], bh[pr][2]);
                mma_bf16(acc[0][pr * 2 + 1], ah0, bh[pr][1], bh[pr][3]);
                mma_bf16(acc[1][pr * 2],     ah1, bh[pr][0], bh[pr][2]);
                mma_bf16(acc[1][pr * 2 + 1], ah1, bh[pr][1], bh[pr][3]);
                // lo * hi
                mma_bf16(acc[0][pr * 2],     al0, bh[pr][0], bh[pr][2]);
                mma_bf16(acc[0][pr * 2 + 1], al0, bh[pr][1], bh[pr][3]);
                mma_bf16(acc[1][pr * 2],     al1, bh[pr][0], bh[pr][2]);
                mma_bf16(acc[1][pr * 2 + 1], al1, bh[pr][1], bh[pr][3]);
                // hi * lo
                mma_bf16(acc[0][pr * 2],     ah0, bl[pr][0], bl[pr][2]);
                mma_bf16(acc[0][pr * 2 + 1], ah0, bl[pr][1], bl[pr][3]);
                mma_bf16(acc[1][pr * 2],     ah1, bl[pr][0], bl[pr][2]);
                mma_bf16(acc[1][pr * 2 + 1], ah1, bl[pr][1], bl[pr][3]);
            }
        }
    }

    // ---- epilogue ----
    float2 bv[8];
#pragma unroll
    for (int nt = 0; nt < 8; nt++) bv[nt] = make_float2(0.f, 0.f);
    if (c == 0) {
#pragma unroll
        for (int nt = 0; nt < 8; nt++) {
            int nn = wn * 64 + nt * 8 + (lane & 3) * 2;
            bv[nt] = *(const float2*)&bias[nn];
        }
    }
#pragma unroll
    for (int mt = 0; mt < 2; mt++) {
        int r0 = row0 + wm * 32 + mt * 16 + (lane >> 2);
        int r1 = r0 + 8;
#pragma unroll
        for (int nt = 0; nt < 8; nt++) {
            int nn = wn * 64 + nt * 8 + (lane & 3) * 2;
            if (r0 < n) {
                float2 v = make_float2(acc[mt][nt][0] + bv[nt].x,
                                       acc[mt][nt][1] + bv[nt].y);
                *(float2*)&out[((size_t)r0 * 4 + c) * 128 + nn] = v;
            }
            if (r1 < n) {
                float2 v = make_float2(acc[mt][nt][2] + bv[nt].x,
                                       acc[mt][nt][3] + bv[nt].y);
                *(float2*)&out[((size_t)r1 * 4 + c) * 128 + nn] = v;
            }
        }
    }
}

// ---------------- launch -----------------------------------------------------

extern "C" void kernel_launch(void* const* d_in, const int* in_sizes, int n_in,
                              void* d_out, int out_size) {
    const float* x      = (const float*)d_in[0];
    const void*  ei     = d_in[1];
    const float* Wsrel  = (const float*)d_in[2];
    const float* Wsroot = (const float*)d_in[3];
    const float* bs     = (const float*)d_in[4];
    const float* Wvrel  = (const float*)d_in[5];
    const float* Wvroot = (const float*)d_in[6];
    float*       out    = (float*)d_out;

    int n = in_sizes[0] / (4 * HDIM);   // 50000
    int e = in_sizes[1] / 2;            // 500000
    int nb = (n + 255) / 256;

    cudaFuncSetAttribute(hmma_gemm_kernel,
                         cudaFuncAttributeMaxDynamicSharedMemorySize, SM_TOT);

    detect_kernel<<<1, 1>>>(ei, e, n);

    zero_counts_kernel<<<(n + 255) / 256, 256>>>(n);
    count_kernel<<<(e + 255) / 256, 256>>>(ei, e);
    scan1_kernel<<<nb, 256>>>(n);
    scan2_kernel<<<1, 256>>>(nb);
    scan3_kernel<<<nb, 256>>>(n);
    fill_kernel<<<(e + 255) / 256, 256>>>(ei, e);

    wprep_kernel<<<(4 * 128 * 256 + 255) / 256, 256>>>(Wsrel, Wsroot, Wvrel, Wvroot);

    dim3 grid((n + 127) / 128, 4);
    hmma_gemm_kernel<<<grid, 256, SM_TOT>>>(x, bs, out, n);
}

// round 15
// speedup vs baseline: 1.2088x; 1.2088x over previous
#include <cuda_runtime.h>
#include <cuda_bf16.h>
#include <cstdint>

// Problem constants
#define MAXN 50000
#define MAXE 500000
#define HDIM 128

// ---------------- scratch (device globals) -----------------------------------
__device__ int   g_is64;
__device__ int   g_counts [MAXN];
__device__ int   g_offsets[MAXN + 1];
__device__ int   g_cursor [MAXN];
__device__ int   g_sorted [MAXE];
__device__ int   g_bsum   [256];
__device__ int   g_boff   [256];
__device__ int   g_total;
__device__ float g_agg    [(size_t)MAXN * 4 * HDIM];          // [n][c][h], 102.4 MB
// bf16 split weights, [c][o][k256]: k<128 -> Wroot[o][k], else Wrel[o][k-128]
__device__ __nv_bfloat16 g_whi[4 * 128 * 256];
__device__ __nv_bfloat16 g_wlo[4 * 128 * 256];

// ---------------- helpers ------------------------------------------------------
__device__ __forceinline__ uint32_t smem_u32(const void* p) {
    uint32_t a;
    asm("{ .reg .u64 t; cvta.to.shared.u64 t, %1; cvt.u32.u64 %0, t; }"
        : "=r"(a) : "l"(p));
    return a;
}

__device__ __forceinline__ void ldsm_x4(uint32_t* r, uint32_t addr) {
    asm volatile("ldmatrix.sync.aligned.m8n8.x4.shared.b16 {%0,%1,%2,%3}, [%4];"
                 : "=r"(r[0]), "=r"(r[1]), "=r"(r[2]), "=r"(r[3]) : "r"(addr));
}
__device__ __forceinline__ void mma_bf16(float* d, const uint32_t* a,
                                         uint32_t b0, uint32_t b1) {
    asm volatile(
        "mma.sync.aligned.m16n8k16.row.col.f32.bf16.bf16.f32 "
        "{%0,%1,%2,%3}, {%4,%5,%6,%7}, {%8,%9}, {%0,%1,%2,%3};"
        : "+f"(d[0]), "+f"(d[1]), "+f"(d[2]), "+f"(d[3])
        : "r"(a[0]), "r"(a[1]), "r"(a[2]), "r"(a[3]), "r"(b0), "r"(b1));
}
__device__ __forceinline__ void cp_async16(uint32_t dst, const void* src) {
    asm volatile("cp.async.ca.shared.global [%0], [%1], 16;"
                 :: "r"(dst), "l"(src) : "memory");
}
#define CP_COMMIT() asm volatile("cp.async.commit_group;" ::: "memory")
#define CP_WAIT0()  asm volatile("cp.async.wait_group 0;" ::: "memory")

// ---------------- CSR kernels --------------------------------------------------
__global__ void detect_kernel(const void* __restrict__ ei, int e, int n) {
    int i = threadIdx.x;                 // 256 threads
    const long long* p64 = (const long long*)ei;
    int cnt = e < 256 ? e : 256;
    int bad = 0;
    if (i < cnt) {
        long long v = p64[i];
        bad = (v < 0 || v >= (long long)n) ? 1 : 0;
    }
    int any = __syncthreads_or(bad);
    if (i == 0) g_is64 = !any;
}

__global__ void zero_counts_kernel(int n) {
    int i = blockIdx.x * blockDim.x + threadIdx.x;
    if (i < n) g_counts[i] = 0;
}

__global__ void count_kernel(const void* __restrict__ ei, int e) {
    int i = blockIdx.x * blockDim.x + threadIdx.x;
    if (i < e) {
        int r;
        if (g_is64) r = (int)((const long long*)ei)[i];
        else        r = ((const int*)ei)[i];
        atomicAdd(&g_counts[r], 1);
    }
}

__global__ void scan1_kernel(int n) {
    int tid  = threadIdx.x;
    int gid  = blockIdx.x * 256 + tid;
    int lane = tid & 31;
    int wid  = tid >> 5;
    int v = (gid < n) ? g_counts[gid] : 0;
    int s = v;
#pragma unroll
    for (int o = 1; o < 32; o <<= 1) {
        int t = __shfl_up_sync(0xFFFFFFFFu, s, o);
        if (lane >= o) s += t;
    }
    __shared__ int wtot[8];
    __shared__ int woff[8];
    if (lane == 31) wtot[wid] = s;
    __syncthreads();
    if (tid == 0) {
        int r = 0;
#pragma unroll
        for (int w = 0; w < 8; w++) { woff[w] = r; r += wtot[w]; }
        g_bsum[blockIdx.x] = r;
    }
    __syncthreads();
    int excl = s - v + woff[wid];
    if (gid < n) g_offsets[gid] = excl;
}

__global__ void scan2_kernel(int nb) {
    int tid  = threadIdx.x;
    int lane = tid & 31;
    int wid  = tid >> 5;
    int v = (tid < nb) ? g_bsum[tid] : 0;
    int s = v;
#pragma unroll
    for (int o = 1; o < 32; o <<= 1) {
        int t = __shfl_up_sync(0xFFFFFFFFu, s, o);
        if (lane >= o) s += t;
    }
    __shared__ int wtot[8];
    __shared__ int woff[8];
    if (lane == 31) wtot[wid] = s;
    __syncthreads();
    if (tid == 0) {
        int r = 0;
#pragma unroll
        for (int w = 0; w < 8; w++) { woff[w] = r; r += wtot[w]; }
        g_total = r;
    }
    __syncthreads();
    g_boff[tid] = s - v + woff[wid];
}

__global__ void scan3_kernel(int n) {
    int gid = blockIdx.x * 256 + threadIdx.x;
    if (gid < n) {
        int off = g_offsets[gid] + g_boff[gid >> 8];
        g_offsets[gid] = off;
        g_cursor[gid]  = off;
    }
    if (gid == 0) g_offsets[n] = g_total;
}

__global__ void fill_kernel(const void* __restrict__ ei, int e) {
    int i = blockIdx.x * blockDim.x + threadIdx.x;
    if (i < e) {
        int r, c;
        if (g_is64) {
            const long long* p = (const long long*)ei;
            r = (int)p[i];
            c = (int)p[(size_t)e + i];
        } else {
            const int* p = (const int*)ei;
            r = p[i];
            c = p[(size_t)e + i];
        }
        int pos = atomicAdd(&g_cursor[r], 1);
        g_sorted[pos] = c;
    }
}

// one block (128 threads) per node; unroll-4 gather; streaming store so the
// g_agg write-allocate doesn't evict x (102MB, L2-resident) from L2.
__global__ void agg_kernel(const float* __restrict__ x) {
    int nidx = blockIdx.x;
    int tid  = threadIdx.x;
    int beg = g_offsets[nidx];
    int end = g_offsets[nidx + 1];
    const float4* xv = (const float4*)x;
    float4 acc = make_float4(0.f, 0.f, 0.f, 0.f);
    int j = beg;
    for (; j + 3 < end; j += 4) {
        int c0 = g_sorted[j];
        int c1 = g_sorted[j + 1];
        int c2 = g_sorted[j + 2];
        int c3 = g_sorted[j + 3];
        float4 v0 = xv[(size_t)c0 * 128 + tid];
        float4 v1 = xv[(size_t)c1 * 128 + tid];
        float4 v2 = xv[(size_t)c2 * 128 + tid];
        float4 v3 = xv[(size_t)c3 * 128 + tid];
        acc.x += v0.x; acc.y += v0.y; acc.z += v0.z; acc.w += v0.w;
        acc.x += v1.x; acc.y += v1.y; acc.z += v1.z; acc.w += v1.w;
        acc.x += v2.x; acc.y += v2.y; acc.z += v2.z; acc.w += v2.w;
        acc.x += v3.x; acc.y += v3.y; acc.z += v3.z; acc.w += v3.w;
    }
    for (; j < end; j++) {
        int c0 = g_sorted[j];
        float4 v0 = xv[(size_t)c0 * 128 + tid];
        acc.x += v0.x; acc.y += v0.y; acc.z += v0.z; acc.w += v0.w;
    }
    __stcs(((float4*)g_agg) + (size_t)nidx * 128 + tid, acc);
}

// weight prep: bf16 hi/lo split, [c][o][k256]
__global__ void wprep_kernel(const float* __restrict__ Wsrel,
                             const float* __restrict__ Wsroot,
                             const float* __restrict__ Wvrel,
                             const float* __restrict__ Wvroot) {
    int idx = blockIdx.x * blockDim.x + threadIdx.x;
    const int total = 4 * 128 * 256;
    if (idx >= total) return;
    int k = idx & 255;
    int o = (idx >> 8) & 127;
    int c = idx >> 15;
    const float* root = (c == 0) ? Wsroot : Wvroot;
    const float* rel  = (c == 0) ? Wsrel  : Wvrel;
    float w = (k < 128) ? root[o * 128 + k] : rel[o * 128 + (k - 128)];
    __nv_bfloat16 hi = __float2bfloat16(w);
    __nv_bfloat16 lo = __float2bfloat16(w - __bfloat162float(hi));
    g_whi[idx] = hi;
    g_wlo[idx] = lo;
}

// ---------------- pipelined HMMA GEMM -------------------------------------------
// grid (ceil(n/128), 4), 256 threads (8 warps 4x2), dyn smem 128KB (2 buffers).
// out[n,c,:] = [x | agg](n,c,:) @ Wcat_c^T (+bias if c==0), bf16 split 3-product.
// Software pipeline: while computing chunk k from buffer k%2, chunk k+1's A is
// LDG'd into registers and its B tiles stream in via cp.async into buffer
// (k+1)%2; after the MMAs, A is converted+stored; one barrier per chunk.

#define SM_AHI 0
#define SM_ALO 16384
#define SM_BHI 32768
#define SM_BLO 49152
#define BUFSZ  65536
#define SM_TOT 131072

__global__ __launch_bounds__(256) void hmma_gemm_kernel(const float* __restrict__ x,
                                                        const float* __restrict__ bias,
                                                        float* __restrict__ out,
                                                        int n) {
    extern __shared__ char smem[];
    uint32_t sb = smem_u32(smem);

    int tid  = threadIdx.x;
    int lane = tid & 31;
    int warp = tid >> 5;
    int wm   = warp & 3;     // 0..3  -> 32 M rows each
    int wn   = warp >> 2;    // 0..1  -> 64 N cols each
    int c    = blockIdx.y;
    int row0 = blockIdx.x * 128;

    int q   = lane >> 3;     // ldmatrix lane group
    int rib = lane & 7;
    int qm  = (q & 1) * 8;
    int qk  = q >> 1;

    // fixed ldmatrix row indices
    int rA0 = wm * 32 + qm + rib;
    int rA1 = rA0 + 16;
    int rB[4];
#pragma unroll
    for (int p = 0; p < 4; p++) rB[p] = wn * 64 + p * 16 + qm + rib;

    float acc[2][8][4];
#pragma unroll
    for (int mt = 0; mt < 2; mt++)
#pragma unroll
        for (int nt = 0; nt < 8; nt++)
#pragma unroll
            for (int i = 0; i < 4; i++) acc[mt][nt][i] = 0.f;

    float4 av[8];   // register staging for the A chunk in flight

    // ---- issue A-chunk global loads into registers ----
    auto ldgA = [&](int k0c) {
        const float* asrc = (k0c < 2) ? x : (const float*)g_agg;
        int kbase = (k0c & 1) * 64;
#pragma unroll
        for (int it = 0; it < 8; it++) {
            int idx = it * 256 + tid;
            int r   = idx >> 4;           // 0..127
            int f4  = idx & 15;
            int nn  = row0 + r;
            av[it] = (nn < n)
                ? *(const float4*)&asrc[((size_t)nn * 4 + c) * 128 + kbase + f4 * 4]
                : make_float4(0.f, 0.f, 0.f, 0.f);
        }
    };

    // ---- convert + store staged A into buffer b ----
    auto stsA = [&](int b) {
        uint32_t base = (uint32_t)(b * BUFSZ);
#pragma unroll
        for (int it = 0; it < 8; it++) {
            int idx = it * 256 + tid;
            int r   = idx >> 4;
            int f4  = idx & 15;
            float4 v = av[it];
            __nv_bfloat16 h0 = __float2bfloat16(v.x);
            __nv_bfloat16 h1 = __float2bfloat16(v.y);
            __nv_bfloat16 h2 = __float2bfloat16(v.z);
            __nv_bfloat16 h3 = __float2bfloat16(v.w);
            __nv_bfloat16 l0 = __float2bfloat16(v.x - __bfloat162float(h0));
            __nv_bfloat16 l1 = __float2bfloat16(v.y - __bfloat162float(h1));
            __nv_bfloat16 l2 = __float2bfloat16(v.z - __bfloat162float(h2));
            __nv_bfloat16 l3 = __float2bfloat16(v.w - __bfloat162float(h3));
            uint2 hv, lv;
            hv.x = (uint32_t)__bfloat16_as_ushort(h0) | ((uint32_t)__bfloat16_as_ushort(h1) << 16);
            hv.y = (uint32_t)__bfloat16_as_ushort(h2) | ((uint32_t)__bfloat16_as_ushort(h3) << 16);
            lv.x = (uint32_t)__bfloat16_as_ushort(l0) | ((uint32_t)__bfloat16_as_ushort(l1) << 16);
            lv.y = (uint32_t)__bfloat16_as_ushort(l2) | ((uint32_t)__bfloat16_as_ushort(l3) << 16);
            int kc   = f4 >> 1;
            int sub8 = (f4 & 1) << 3;
            uint32_t off = base + (uint32_t)(r * 128 + ((kc ^ (r & 7)) << 4) + sub8);
            *(uint2*)(smem + SM_AHI + off) = hv;
            *(uint2*)(smem + SM_ALO + off) = lv;
        }
    };

    // ---- stream B chunk into buffer b via cp.async ----
    auto cpB = [&](int k0c, int b) {
        const __nv_bfloat16* wh = g_whi + (size_t)c * 128 * 256 + k0c * 64;
        const __nv_bfloat16* wl = g_wlo + (size_t)c * 128 * 256 + k0c * 64;
        uint32_t base = (uint32_t)(b * BUFSZ);
#pragma unroll
        for (int it = 0; it < 4; it++) {
            int id = it * 256 + tid;
            int nr = id >> 3;             // 0..127
            int kc = id & 7;              // 16B chunk
            uint32_t off = base + (uint32_t)(nr * 128 + ((kc ^ (nr & 7)) << 4));
            cp_async16(sb + SM_BHI + off, wh + (size_t)nr * 256 + kc * 8);
            cp_async16(sb + SM_BLO + off, wl + (size_t)nr * 256 + kc * 8);
        }
        CP_COMMIT();
    };

    // ---- MMA compute on buffer b ----
    auto compute = [&](int b) {
        uint32_t base = sb + (uint32_t)(b * BUFSZ);
#pragma unroll
        for (int ks = 0; ks < 4; ks++) {
            int kc = ks * 2 + qk;
            uint32_t ah0[4], ah1[4], al0[4], al1[4];
            uint32_t offA0 = (uint32_t)(rA0 * 128 + ((kc ^ (rA0 & 7)) << 4));
            uint32_t offA1 = (uint32_t)(rA1 * 128 + ((kc ^ (rA1 & 7)) << 4));
            ldsm_x4(ah0, base + SM_AHI + offA0);
            ldsm_x4(ah1, base + SM_AHI + offA1);
            ldsm_x4(al0, base + SM_ALO + offA0);
            ldsm_x4(al1, base + SM_ALO + offA1);
            uint32_t bh[4][4], bl[4][4];
#pragma unroll
            for (int pr = 0; pr < 4; pr++) {
                uint32_t offB = (uint32_t)(rB[pr] * 128 + ((kc ^ (rB[pr] & 7)) << 4));
                ldsm_x4(bh[pr], base + SM_BHI + offB);
                ldsm_x4(bl[pr], base + SM_BLO + offB);
            }
#pragma unroll
            for (int pr = 0; pr < 4; pr++) {
                // hi * hi
                mma_bf16(acc[0][pr * 2],     ah0, bh[pr][0], bh[pr][2]);
                mma_bf16(acc[0][pr * 2 + 1], ah0, bh[pr][1], bh[pr][3]);
                mma_bf16(acc[1][pr * 2],     ah1, bh[pr][0], bh[pr][2]);
                mma_bf16(acc[1][pr * 2 + 1], ah1, bh[pr][1], bh[pr][3]);
                // lo * hi
                mma_bf16(acc[0][pr * 2],     al0, bh[pr][0], bh[pr][2]);
                mma_bf16(acc[0][pr * 2 + 1], al0, bh[pr][1], bh[pr][3]);
                mma_bf16(acc[1][pr * 2],     al1, bh[pr][0], bh[pr][2]);
                mma_bf16(acc[1][pr * 2 + 1], al1, bh[pr][1], bh[pr][3]);
                // hi * lo
                mma_bf16(acc[0][pr * 2],     ah0, bl[pr][0], bl[pr][2]);
                mma_bf16(acc[0][pr * 2 + 1], ah0, bl[pr][1], bl[pr][3]);
                mma_bf16(acc[1][pr * 2],     ah1, bl[pr][0], bl[pr][2]);
                mma_bf16(acc[1][pr * 2 + 1], ah1, bl[pr][1], bl[pr][3]);
            }
        }
    };

    // ---- pipeline ----
    ldgA(0);
    cpB(0, 0);
    stsA(0);
    CP_WAIT0();
    __syncthreads();

    for (int k = 0; k < 4; k++) {
        if (k < 3) {
            ldgA(k + 1);             // LDGs in flight during compute
            cpB(k + 1, (k + 1) & 1); // cp.async in flight during compute
        }
        compute(k & 1);
        if (k < 3) {
            stsA((k + 1) & 1);
            CP_WAIT0();
        }
        __syncthreads();
    }

    // ---- epilogue ----
    float2 bv[8];
#pragma unroll
    for (int nt = 0; nt < 8; nt++) bv[nt] = make_float2(0.f, 0.f);
    if (c == 0) {
#pragma unroll
        for (int nt = 0; nt < 8; nt++) {
            int nn = wn * 64 + nt * 8 + (lane & 3) * 2;
            bv[nt] = *(const float2*)&bias[nn];
        }
    }
#pragma unroll
    for (int mt = 0; mt < 2; mt++) {
        int r0 = row0 + wm * 32 + mt * 16 + (lane >> 2);
        int r1 = r0 + 8;
#pragma unroll
        for (int nt = 0; nt < 8; nt++) {
            int nn = wn * 64 + nt * 8 + (lane & 3) * 2;
            if (r0 < n) {
                float2 v = make_float2(acc[mt][nt][0] + bv[nt].x,
                                       acc[mt][nt][1] + bv[nt].y);
                *(float2*)&out[((size_t)r0 * 4 + c) * 128 + nn] = v;
            }
            if (r1 < n) {
                float2 v = make_float2(acc[mt][nt][2] + bv[nt].x,
                                       acc[mt][nt][3] + bv[nt].y);
                *(float2*)&out[((size_t)r1 * 4 + c) * 128 + nn] = v;
            }
        }
    }
}

// ---------------- launch -----------------------------------------------------

extern "C" void kernel_launch(void* const* d_in, const int* in_sizes, int n_in,
                              void* d_out, int out_size) {
    const float* x      = (const float*)d_in[0];
    const void*  ei     = d_in[1];
    const float* Wsrel  = (const float*)d_in[2];
    const float* Wsroot = (const float*)d_in[3];
    const float* bs     = (const float*)d_in[4];
    const float* Wvrel  = (const float*)d_in[5];
    const float* Wvroot = (const float*)d_in[6];
    float*       out    = (float*)d_out;

    int n = in_sizes[0] / (4 * HDIM);   // 50000
    int e = in_sizes[1] / 2;            // 500000
    int nb = (n + 255) / 256;

    cudaFuncSetAttribute(hmma_gemm_kernel,
                         cudaFuncAttributeMaxDynamicSharedMemorySize, SM_TOT);

    detect_kernel<<<1, 256>>>(ei, e, n);

    zero_counts_kernel<<<(n + 255) / 256, 256>>>(n);
    count_kernel<<<(e + 255) / 256, 256>>>(ei, e);
    scan1_kernel<<<nb, 256>>>(n);
    scan2_kernel<<<1, 256>>>(nb);
    scan3_kernel<<<nb, 256>>>(n);
    fill_kernel<<<(e + 255) / 256, 256>>>(ei, e);

    wprep_kernel<<<(4 * 128 * 256 + 255) / 256, 256>>>(Wsrel, Wsroot, Wvrel, Wvroot);

    agg_kernel<<<n, 128>>>(x);

    dim3 grid((n + 127) / 128, 4);
    hmma_gemm_kernel<<<grid, 256, SM_TOT>>>(x, bs, out, n);
}